// round 2
// baseline (speedup 1.0000x reference)
#include <cuda_runtime.h>

#define BB 2
#define CC 256
#define HH 512
#define WW 512
#define HW (HH*WW)
#define ITERS 5

// trimap constants (from int(512*0.1)=51, int(512*0.45)=230, int(512*0.55)=281)
#define BORD 51
#define C0 230
#define C1 281

// ---------------- scratch (no allocations allowed) ----------------
__device__ int            g_minmax[BB][2];          // [b][0]=min bits, [b][1]=max bits
__device__ unsigned       g_total[BB][3];           // exact total channel sums (u32)
__device__ unsigned       g_fg[ITERS][BB][4];       // per-iter fg sums: s0,s1,s2,count
__device__ uchar4         g_img[BB*HW];             // normalized pixels (r,g,b,0)
__device__ unsigned char  g_state[2][BB*HW];        // bit0=alpha, bit1=fixed, bit2=fixed_fg

// ---------------- helpers ----------------
__device__ __forceinline__ void atomicMinF(int* addr, float v) {
    if (v >= 0.0f) atomicMin(addr, __float_as_int(v));
    else           atomicMax((unsigned*)addr, (unsigned)__float_as_int(v));
}
__device__ __forceinline__ void atomicMaxF(int* addr, float v) {
    if (v >= 0.0f) atomicMax(addr, __float_as_int(v));
    else           atomicMin((unsigned*)addr, (unsigned)__float_as_int(v));
}
__device__ __forceinline__ unsigned warpSum(unsigned v) {
#pragma unroll
    for (int o = 16; o; o >>= 1) v += __shfl_xor_sync(0xffffffffu, v, o);
    return v;
}

// ---------------- kernels ----------------
__global__ void k_zero() {
    int t = threadIdx.x;
    if (t < BB) { g_minmax[t][0] = 0x7F800000; g_minmax[t][1] = (int)0xFF800000; }
    // zero totals and per-iteration sums
    unsigned* p = &g_total[0][0];
    for (int i = t; i < BB*3; i += blockDim.x) p[i] = 0u;
    unsigned* q = &g_fg[0][0][0];
    for (int i = t; i < ITERS*BB*4; i += blockDim.x) q[i] = 0u;
}

__global__ void k_minmax(const float* __restrict__ f) {
    int b = blockIdx.y;
    const float4* p = (const float4*)(f + (size_t)b * CC * HW);
    const int n = 3 * HW / 4;
    float mn = __int_as_float(0x7F800000);
    float mx = __int_as_float(0xFF800000);
    for (int i = blockIdx.x * blockDim.x + threadIdx.x; i < n; i += gridDim.x * blockDim.x) {
        float4 v = p[i];
        mn = fminf(mn, fminf(fminf(v.x, v.y), fminf(v.z, v.w)));
        mx = fmaxf(mx, fmaxf(fmaxf(v.x, v.y), fmaxf(v.z, v.w)));
    }
#pragma unroll
    for (int o = 16; o; o >>= 1) {
        mn = fminf(mn, __shfl_xor_sync(0xffffffffu, mn, o));
        mx = fmaxf(mx, __shfl_xor_sync(0xffffffffu, mx, o));
    }
    __shared__ float smn[8], smx[8];
    int lane = threadIdx.x & 31, w = threadIdx.x >> 5;
    if (lane == 0) { smn[w] = mn; smx[w] = mx; }
    __syncthreads();
    if (threadIdx.x == 0) {
        int nw = blockDim.x >> 5;
        for (int i = 1; i < nw; i++) { mn = fminf(mn, smn[i]); mx = fmaxf(mx, smx[i]); }
        atomicMinF(&g_minmax[b][0], mn);
        atomicMaxF(&g_minmax[b][1], mx);
    }
}

__device__ __forceinline__ float quantize(float x, float mn, float den) {
    float v = __fmul_rn(__fdiv_rn(__fsub_rn(x, mn), den), 255.0f);
    return fminf(fmaxf(floorf(v), 0.0f), 255.0f);
}

__global__ void k_prepare(const float* __restrict__ f, const int* __restrict__ mask) {
    int b = blockIdx.y;
    float mn  = __int_as_float(g_minmax[b][0]);
    float mx  = __int_as_float(g_minmax[b][1]);
    float den = __fadd_rn(__fsub_rn(mx, mn), 1e-12f);
    const float* p0 = f + (size_t)b * CC * HW;
    const float* p1 = p0 + HW;
    const float* p2 = p0 + 2 * HW;
    const int* mb = mask + (size_t)b * HW;
    unsigned s0 = 0, s1 = 0, s2 = 0;
    for (int i = blockIdx.x * blockDim.x + threadIdx.x; i < HW; i += gridDim.x * blockDim.x) {
        float q0 = quantize(p0[i], mn, den);
        float q1 = quantize(p1[i], mn, den);
        float q2 = quantize(p2[i], mn, den);
        unsigned u0 = (unsigned)q0, u1 = (unsigned)q1, u2 = (unsigned)q2;
        int r = i >> 9, c = i & (WW - 1);
        unsigned char st;
        bool center = (r >= C0 && r < C1 && c >= C0 && c < C1);
        bool border = (r < BORD || r >= HH - BORD || c < BORD || c >= WW - BORD);
        if (center)      st = 7;               // alpha=1, fixed, fixed_fg=1
        else if (border) st = 2;               // alpha=0, fixed, fixed_fg=0
        else             st = (mb[i] == 1) ? 1 : 0;
        g_img[b * HW + i] = make_uchar4((unsigned char)u0, (unsigned char)u1, (unsigned char)u2, 0);
        g_state[0][b * HW + i] = st;
        s0 += u0; s1 += u1; s2 += u2;
    }
    s0 = warpSum(s0); s1 = warpSum(s1); s2 = warpSum(s2);
    __shared__ unsigned sh[3];
    if (threadIdx.x < 3) sh[threadIdx.x] = 0u;
    __syncthreads();
    if ((threadIdx.x & 31) == 0) {
        atomicAdd(&sh[0], s0); atomicAdd(&sh[1], s1); atomicAdd(&sh[2], s2);
    }
    __syncthreads();
    if (threadIdx.x < 3) atomicAdd(&g_total[b][threadIdx.x], sh[threadIdx.x]);
}

__global__ void k_reduce(int it, int cur) {
    int b = blockIdx.y;
    const unsigned char* st = g_state[cur] + (size_t)b * HW;
    const uchar4* im = g_img + (size_t)b * HW;
    unsigned s0 = 0, s1 = 0, s2 = 0, cnt = 0;
    for (int i = blockIdx.x * blockDim.x + threadIdx.x; i < HW; i += gridDim.x * blockDim.x) {
        if (st[i] & 1u) {
            uchar4 v = im[i];
            s0 += v.x; s1 += v.y; s2 += v.z; cnt++;
        }
    }
    s0 = warpSum(s0); s1 = warpSum(s1); s2 = warpSum(s2); cnt = warpSum(cnt);
    __shared__ unsigned sh[4];
    if (threadIdx.x < 4) sh[threadIdx.x] = 0u;
    __syncthreads();
    if ((threadIdx.x & 31) == 0) {
        atomicAdd(&sh[0], s0); atomicAdd(&sh[1], s1);
        atomicAdd(&sh[2], s2); atomicAdd(&sh[3], cnt);
    }
    __syncthreads();
    if (threadIdx.x < 4) atomicAdd(&g_fg[it][b][threadIdx.x], sh[threadIdx.x]);
}

__global__ void k_update(int it, int cur, float* __restrict__ out) {
    int b = blockIdx.y;
    __shared__ float fm0, fm1, fm2, bm0, bm1, bm2;
    if (threadIdx.x == 0) {
        unsigned fs0 = g_fg[it][b][0], fs1 = g_fg[it][b][1];
        unsigned fs2 = g_fg[it][b][2], fc  = g_fg[it][b][3];
        // JAX: mean = f32_sum / (f32_count + 1e-6); integer sums are exact, RN at convert.
        float fden = __fadd_rn(__uint2float_rn(fc), 1e-6f);
        fm0 = __fdiv_rn(__uint2float_rn(fs0), fden);
        fm1 = __fdiv_rn(__uint2float_rn(fs1), fden);
        fm2 = __fdiv_rn(__uint2float_rn(fs2), fden);
        unsigned bs0 = g_total[b][0] - fs0;
        unsigned bs1 = g_total[b][1] - fs1;
        unsigned bs2 = g_total[b][2] - fs2;
        float bden = __fadd_rn(__uint2float_rn((unsigned)HW - fc), 1e-6f);
        bm0 = __fdiv_rn(__uint2float_rn(bs0), bden);
        bm1 = __fdiv_rn(__uint2float_rn(bs1), bden);
        bm2 = __fdiv_rn(__uint2float_rn(bs2), bden);
    }
    __syncthreads();
    const unsigned char* cs = g_state[cur] + (size_t)b * HW;
    unsigned char* ns = g_state[cur ^ 1] + (size_t)b * HW;
    const uchar4* im = g_img + (size_t)b * HW;
    bool last = (it == ITERS - 1);
    float* ob = out + (size_t)b * HW;
    for (int i = blockIdx.x * blockDim.x + threadIdx.x; i < HW; i += gridDim.x * blockDim.x) {
        int r = i >> 9, c = i & (WW - 1);
        unsigned char st = cs[i];
        unsigned na;
        if (st & 2u) {
            na = (st >> 2) & 1u;   // fixed pixel: alpha = fixed_fg forever
        } else {
            uchar4 v = im[i];
            // d_fg/d_bg with JAX op order: sub, square, left-assoc sum over 3 channels
            float t0 = __fsub_rn((float)v.x, fm0);
            float t1 = __fsub_rn((float)v.y, fm1);
            float t2 = __fsub_rn((float)v.z, fm2);
            float dfg = __fadd_rn(__fadd_rn(__fmul_rn(t0, t0), __fmul_rn(t1, t1)), __fmul_rn(t2, t2));
            float u0 = __fsub_rn((float)v.x, bm0);
            float u1 = __fsub_rn((float)v.y, bm1);
            float u2 = __fsub_rn((float)v.z, bm2);
            float dbg = __fadd_rn(__fadd_rn(__fmul_rn(u0, u0), __fmul_rn(u1, u1)), __fmul_rn(u2, u2));
            // neighbor mean with edge replication, JAX add order (up+down+left+right)*0.25
            int iu = (r > 0)      ? i - WW : i;
            int id = (r < HH - 1) ? i + WW : i;
            int il = (c > 0)      ? i - 1  : i;
            int ir = (c < WW - 1) ? i + 1  : i;
            unsigned nsum = (unsigned)(cs[iu] & 1u) + (cs[id] & 1u) + (cs[il] & 1u) + (cs[ir] & 1u);
            float nb = __fmul_rn(__uint2float_rn(nsum), 0.25f);
            float sm = __fmul_rn(50.0f, __fsub_rn(__fmul_rn(2.0f, nb), 1.0f));
            float score = __fadd_rn(__fsub_rn(dbg, dfg), sm);
            na = (score > 0.0f) ? 1u : 0u;
        }
        if (last) ob[i] = (float)na;
        else      ns[i] = (unsigned char)((st & 6u) | na);
    }
}

// ---------------- launch ----------------
extern "C" void kernel_launch(void* const* d_in, const int* in_sizes, int n_in,
                              void* d_out, int out_size) {
    const float* features = (const float*)d_in[0];
    const int*   mask     = (const int*)d_in[1];
    float*       out      = (float*)d_out;

    k_zero<<<1, 64>>>();
    k_minmax<<<dim3(96, BB), 256>>>(features);
    k_prepare<<<dim3(128, BB), 256>>>(features, mask);
    for (int it = 0; it < ITERS; it++) {
        int cur = it & 1;
        k_reduce<<<dim3(64, BB), 256>>>(it, cur);
        k_update<<<dim3(256, BB), 256>>>(it, cur, out);
    }
}

// round 7
// speedup vs baseline: 1.5808x; 1.5808x over previous
#include <cuda_runtime.h>

#define BB 2
#define CC 256
#define HH 512
#define WW 512
#define HW (HH*WW)
#define ITERS 5

// trimap constants (int(512*0.1)=51, int(512*0.45)=230, int(512*0.55)=281)
#define BORD 51
#define C0 230
#define C1 281

#define NBLK 148
#define PB   (NBLK/BB)      // 74 blocks per batch
#define NTHR 512
#define TPB  (PB*NTHR)      // threads per batch = 37888

// ---------------- scratch (no allocations allowed) ----------------
__device__ unsigned       g_bar_count = 0;
__device__ volatile unsigned g_bar_gen = 0;
__device__ int            g_minmax[BB][2];          // float bits: [0]=min, [1]=max
__device__ unsigned       g_total[BB][3];           // exact total channel sums
__device__ unsigned       g_fg[ITERS+1][BB][4];     // per-iter fg sums: s0,s1,s2,count
__device__ uchar4         g_img[BB*HW];             // normalized pixels (immutable after prepare)
__device__ unsigned char  g_state[2][BB*HW];        // bit0=alpha, bit1=fixed, bit2=fixed_fg

// ---------------- helpers ----------------
__device__ __forceinline__ void grid_sync() {
    __threadfence();        // make this thread's writes visible device-wide
    __syncthreads();
    if (threadIdx.x == 0) {
        unsigned gen = g_bar_gen;
        if (atomicAdd(&g_bar_count, 1) == NBLK - 1) {
            g_bar_count = 0;
            __threadfence();
            g_bar_gen = gen + 1;            // release
        } else {
            while (g_bar_gen == gen) { }    // spin on L2
        }
    }
    __syncthreads();
}

__device__ __forceinline__ void atomicMinF(int* addr, float v) {
    if (v >= 0.0f) atomicMin(addr, __float_as_int(v));
    else           atomicMax((unsigned*)addr, (unsigned)__float_as_int(v));
}
__device__ __forceinline__ void atomicMaxF(int* addr, float v) {
    if (v >= 0.0f) atomicMax(addr, __float_as_int(v));
    else           atomicMin((unsigned*)addr, (unsigned)__float_as_int(v));
}
__device__ __forceinline__ unsigned warpSum(unsigned v) {
#pragma unroll
    for (int o = 16; o; o >>= 1) v += __shfl_xor_sync(0xffffffffu, v, o);
    return v;
}

__device__ __forceinline__ float quantize(float x, float mn, float den) {
    float v = __fmul_rn(__fdiv_rn(__fsub_rn(x, mn), den), 255.0f);
    return fminf(fmaxf(floorf(v), 0.0f), 255.0f);
}

// ---------------- the single persistent kernel ----------------
__global__ void __launch_bounds__(NTHR, 1)
gc_kernel(const float* __restrict__ f, const int* __restrict__ mask,
          float* __restrict__ out)
{
    const int b    = blockIdx.x / PB;          // batch this block serves
    const int blk  = blockIdx.x % PB;
    const int tid  = blk * NTHR + threadIdx.x; // thread id within batch's worker set
    const int lane = threadIdx.x & 31;
    const int wrp  = threadIdx.x >> 5;

    __shared__ float    s_mn[16], s_mx[16];
    __shared__ unsigned s_acc[8];
    __shared__ float    s_means[6];

    // ---- Phase A: init accumulators (block 0 only) ----
    if (blockIdx.x == 0) {
        int t = threadIdx.x;
        if (t < BB) { g_minmax[t][0] = 0x7F800000; g_minmax[t][1] = (int)0xFF800000; }
        unsigned* p = &g_total[0][0];
        for (int i = t; i < BB*3; i += NTHR) p[i] = 0u;
        unsigned* q = &g_fg[0][0][0];
        for (int i = t; i < (ITERS+1)*BB*4; i += NTHR) q[i] = 0u;
    }
    grid_sync();

    // ---- Phase B: per-batch min/max over first 3 channels ----
    {
        const float4* p = (const float4*)(f + (size_t)b * CC * HW);
        const int n = 3 * HW / 4;
        float mn = __int_as_float(0x7F800000);
        float mx = __int_as_float(0xFF800000);
        for (int i = tid; i < n; i += TPB) {
            float4 v = p[i];
            mn = fminf(mn, fminf(fminf(v.x, v.y), fminf(v.z, v.w)));
            mx = fmaxf(mx, fmaxf(fmaxf(v.x, v.y), fmaxf(v.z, v.w)));
        }
#pragma unroll
        for (int o = 16; o; o >>= 1) {
            mn = fminf(mn, __shfl_xor_sync(0xffffffffu, mn, o));
            mx = fmaxf(mx, __shfl_xor_sync(0xffffffffu, mx, o));
        }
        if (lane == 0) { s_mn[wrp] = mn; s_mx[wrp] = mx; }
        __syncthreads();
        if (threadIdx.x == 0) {
            for (int i = 1; i < NTHR/32; i++) { mn = fminf(mn, s_mn[i]); mx = fmaxf(mx, s_mx[i]); }
            atomicMinF(&g_minmax[b][0], mn);
            atomicMaxF(&g_minmax[b][1], mx);
        }
    }
    grid_sync();

    // ---- Phase C: quantize, seed trimap state, exact total + iter-0 fg sums ----
    {
        float mn  = __int_as_float(__ldcg(&g_minmax[b][0]));
        float mx  = __int_as_float(__ldcg(&g_minmax[b][1]));
        float den = __fadd_rn(__fsub_rn(mx, mn), 1e-12f);
        const float* p0 = f + (size_t)b * CC * HW;      // L2-hot (re-read)
        const float* p1 = p0 + HW;
        const float* p2 = p0 + 2 * HW;
        const int* mb = mask + (size_t)b * HW;
        unsigned t0 = 0, t1 = 0, t2 = 0;                 // total sums
        unsigned f0 = 0, f1 = 0, f2 = 0, fc = 0;         // fg (alpha) sums
        for (int i = tid; i < HW; i += TPB) {
            unsigned u0 = (unsigned)quantize(p0[i], mn, den);
            unsigned u1 = (unsigned)quantize(p1[i], mn, den);
            unsigned u2 = (unsigned)quantize(p2[i], mn, den);
            int r = i >> 9, c = i & (WW - 1);
            unsigned char st;
            bool center = (r >= C0 && r < C1 && c >= C0 && c < C1);
            bool border = (r < BORD || r >= HH - BORD || c < BORD || c >= WW - BORD);
            if (center)      st = 7;                     // alpha=1, fixed, fixed_fg
            else if (border) st = 2;                     // alpha=0, fixed
            else             st = (mb[i] == 1) ? 1 : 0;
            g_img[b * HW + i] = make_uchar4((unsigned char)u0, (unsigned char)u1, (unsigned char)u2, 0);
            g_state[0][b * HW + i] = st;
            t0 += u0; t1 += u1; t2 += u2;
            if (st & 1u) { f0 += u0; f1 += u1; f2 += u2; fc++; }
        }
        t0 = warpSum(t0); t1 = warpSum(t1); t2 = warpSum(t2);
        f0 = warpSum(f0); f1 = warpSum(f1); f2 = warpSum(f2); fc = warpSum(fc);
        if (threadIdx.x < 8) s_acc[threadIdx.x] = 0u;
        __syncthreads();
        if (lane == 0) {
            atomicAdd(&s_acc[0], t0); atomicAdd(&s_acc[1], t1); atomicAdd(&s_acc[2], t2);
            atomicAdd(&s_acc[3], f0); atomicAdd(&s_acc[4], f1); atomicAdd(&s_acc[5], f2);
            atomicAdd(&s_acc[6], fc);
        }
        __syncthreads();
        if (threadIdx.x < 3) atomicAdd(&g_total[b][threadIdx.x], s_acc[threadIdx.x]);
        else if (threadIdx.x < 7) atomicAdd(&g_fg[0][b][threadIdx.x - 3], s_acc[threadIdx.x]);
    }
    grid_sync();

    // ---- Phase D: 5 ICM iterations, fused relabel + next-iteration reduction ----
    const uchar4* im = g_img + (size_t)b * HW;
    for (int it = 0; it < ITERS; it++) {
        const bool last = (it == ITERS - 1);
        if (threadIdx.x == 0) {
            unsigned fs0 = __ldcg(&g_fg[it][b][0]), fs1 = __ldcg(&g_fg[it][b][1]);
            unsigned fs2 = __ldcg(&g_fg[it][b][2]), fcn = __ldcg(&g_fg[it][b][3]);
            // JAX: mean = f32(exact integer sum) / (f32(count) + 1e-6)
            float fden = __fadd_rn(__uint2float_rn(fcn), 1e-6f);
            s_means[0] = __fdiv_rn(__uint2float_rn(fs0), fden);
            s_means[1] = __fdiv_rn(__uint2float_rn(fs1), fden);
            s_means[2] = __fdiv_rn(__uint2float_rn(fs2), fden);
            unsigned bs0 = __ldcg(&g_total[b][0]) - fs0;
            unsigned bs1 = __ldcg(&g_total[b][1]) - fs1;
            unsigned bs2 = __ldcg(&g_total[b][2]) - fs2;
            float bden = __fadd_rn(__uint2float_rn((unsigned)HW - fcn), 1e-6f);
            s_means[3] = __fdiv_rn(__uint2float_rn(bs0), bden);
            s_means[4] = __fdiv_rn(__uint2float_rn(bs1), bden);
            s_means[5] = __fdiv_rn(__uint2float_rn(bs2), bden);
        }
        __syncthreads();
        const float fm0 = s_means[0], fm1 = s_means[1], fm2 = s_means[2];
        const float bm0 = s_means[3], bm1 = s_means[4], bm2 = s_means[5];

        const unsigned char* cs = g_state[it & 1] + (size_t)b * HW;
        unsigned char* ns = g_state[(it & 1) ^ 1] + (size_t)b * HW;
        float* ob = out + (size_t)b * HW;

        unsigned a0 = 0, a1 = 0, a2 = 0, ac = 0;
        for (int i = tid; i < HW; i += TPB) {
            int r = i >> 9, c = i & (WW - 1);
            unsigned char st = __ldcg(cs + i);           // mutable: L2-coherent read
            uchar4 v = im[i];                            // immutable: L1-cached
            unsigned na;
            if (st & 2u) {
                na = (st >> 2) & 1u;                     // fixed: alpha = fixed_fg
            } else {
                float t0 = __fsub_rn((float)v.x, fm0);
                float t1 = __fsub_rn((float)v.y, fm1);
                float t2 = __fsub_rn((float)v.z, fm2);
                float dfg = __fadd_rn(__fadd_rn(__fmul_rn(t0, t0), __fmul_rn(t1, t1)), __fmul_rn(t2, t2));
                float u0 = __fsub_rn((float)v.x, bm0);
                float u1 = __fsub_rn((float)v.y, bm1);
                float u2 = __fsub_rn((float)v.z, bm2);
                float dbg = __fadd_rn(__fadd_rn(__fmul_rn(u0, u0), __fmul_rn(u1, u1)), __fmul_rn(u2, u2));
                int iu = (r > 0)      ? i - WW : i;
                int id = (r < HH - 1) ? i + WW : i;
                int il = (c > 0)      ? i - 1  : i;
                int ir = (c < WW - 1) ? i + 1  : i;
                unsigned nsum = (unsigned)(__ldcg(cs + iu) & 1u) + (__ldcg(cs + id) & 1u)
                              + (__ldcg(cs + il) & 1u) + (__ldcg(cs + ir) & 1u);
                float nb = __fmul_rn(__uint2float_rn(nsum), 0.25f);
                float sm = __fmul_rn(50.0f, __fsub_rn(__fmul_rn(2.0f, nb), 1.0f));
                float score = __fadd_rn(__fsub_rn(dbg, dfg), sm);
                na = (score > 0.0f) ? 1u : 0u;
            }
            if (last) {
                ob[i] = (float)na;
            } else {
                ns[i] = (unsigned char)((st & 6u) | na);
                if (na) { a0 += v.x; a1 += v.y; a2 += v.z; ac++; }
            }
        }

        if (!last) {
            a0 = warpSum(a0); a1 = warpSum(a1); a2 = warpSum(a2); ac = warpSum(ac);
            if (threadIdx.x < 4) s_acc[threadIdx.x] = 0u;
            __syncthreads();
            if (lane == 0) {
                atomicAdd(&s_acc[0], a0); atomicAdd(&s_acc[1], a1);
                atomicAdd(&s_acc[2], a2); atomicAdd(&s_acc[3], ac);
            }
            __syncthreads();
            if (threadIdx.x < 4) atomicAdd(&g_fg[it + 1][b][threadIdx.x], s_acc[threadIdx.x]);
            grid_sync();
        }
    }
}

// ---------------- launch ----------------
extern "C" void kernel_launch(void* const* d_in, const int* in_sizes, int n_in,
                              void* d_out, int out_size) {
    const float* features = (const float*)d_in[0];
    const int*   mask     = (const int*)d_in[1];
    float*       out      = (float*)d_out;
    gc_kernel<<<NBLK, NTHR>>>(features, mask, out);
}

// round 8
// speedup vs baseline: 1.6353x; 1.0344x over previous
#include <cuda_runtime.h>

#define BB 2
#define CC 256
#define HH 512
#define WW 512
#define HW (HH*WW)
#define ITERS 5

// trimap constants (int(512*0.1)=51, int(512*0.45)=230, int(512*0.55)=281)
#define BORD 51
#define C0 230
#define C1 281

#define PBB 64              // blocks per batch
#define NBLK (BB*PBB)       // 128 total blocks (< 148 SMs, one wave)
#define NTHR 512
#define RPB 8               // rows per block strip
#define TPB (PBB*NTHR)      // threads per batch

// ---------------- scratch (no allocations allowed) ----------------
__device__ unsigned          g_bar_count = 0;
__device__ volatile unsigned g_bar_gen = 0;
__device__ float2 g_pmm[NBLK];                 // per-block min/max partials
__device__ uint4  g_ptot[NBLK];                // per-block total channel sums
__device__ uint4  g_pfg[ITERS][NBLK];          // per-block fg sums per iteration
__device__ __align__(16) unsigned char g_halo[2][BB][HH][WW];  // boundary rows only

// ---------------- helpers ----------------
__device__ __forceinline__ void grid_sync() {
    __threadfence();
    __syncthreads();
    if (threadIdx.x == 0) {
        unsigned gen = g_bar_gen;
        if (atomicAdd(&g_bar_count, 1) == NBLK - 1) {
            g_bar_count = 0;
            __threadfence();
            g_bar_gen = gen + 1;
        } else {
            while (g_bar_gen == gen) { }
        }
    }
    __syncthreads();
}

__device__ __forceinline__ unsigned warpSum(unsigned v) {
#pragma unroll
    for (int o = 16; o; o >>= 1) v += __shfl_xor_sync(0xffffffffu, v, o);
    return v;
}

__device__ __forceinline__ float quantize(float x, float mn, float den) {
    float v = __fmul_rn(__fdiv_rn(__fsub_rn(x, mn), den), 255.0f);
    return fminf(fmaxf(floorf(v), 0.0f), 255.0f);
}

// ---------------- the single persistent kernel ----------------
__global__ void __launch_bounds__(NTHR, 1)
gc_kernel(const float* __restrict__ f, const int* __restrict__ mask,
          float* __restrict__ out)
{
    const int b    = blockIdx.x / PBB;
    const int blk  = blockIdx.x % PBB;
    const int t    = threadIdx.x;
    const int lane = t & 31;
    const int wrp  = t >> 5;
    const int ty   = t >> 6;            // row within strip (0..7)
    const int tx   = t & 63;            // column group (8 px each)
    const int rs   = blk * RPB;         // strip start row
    const int rr   = rs + ty;           // this thread's row
    const int cb   = tx * 8;            // this thread's first column

    __shared__ __align__(16) unsigned char s_alpha[2][RPB + 2][WW]; // rows: 0=up halo, 1..8=strip, 9=down halo
    __shared__ unsigned s_acc[8];
    __shared__ unsigned s_tot[3];
    __shared__ float    s_means[8];
    __shared__ float    s_red[32];

    if (t < 8) s_acc[t] = 0u;

    // per-thread persistent pixel data (filled in Phase C)
    float fv0[8], fv1[8], fv2[8];                       // quantized pixel values as floats
    unsigned p0lo = 0, p0hi = 0, p1lo = 0, p1hi = 0, p2lo = 0, p2hi = 0; // packed bytes
    unsigned fixedm = 0, ffgm = 0;                      // per-pixel bitmasks

    // ---- Phase B: per-batch min/max over first 3 channels (DRAM read) ----
    {
        const float4* p = (const float4*)(f + (size_t)b * CC * HW);
        const int n = 3 * HW / 4;
        float mn = __int_as_float(0x7F800000);
        float mx = __int_as_float(0xFF800000);
        for (int i = blk * NTHR + t; i < n; i += TPB) {
            float4 v = p[i];
            mn = fminf(mn, fminf(fminf(v.x, v.y), fminf(v.z, v.w)));
            mx = fmaxf(mx, fmaxf(fmaxf(v.x, v.y), fmaxf(v.z, v.w)));
        }
#pragma unroll
        for (int o = 16; o; o >>= 1) {
            mn = fminf(mn, __shfl_xor_sync(0xffffffffu, mn, o));
            mx = fmaxf(mx, __shfl_xor_sync(0xffffffffu, mx, o));
        }
        if (lane == 0) { s_red[wrp] = mn; s_red[16 + wrp] = mx; }
        __syncthreads();
        if (t == 0) {
            for (int i = 1; i < 16; i++) { mn = fminf(mn, s_red[i]); mx = fmaxf(mx, s_red[16 + i]); }
            g_pmm[blockIdx.x] = make_float2(mn, mx);
        }
    }
    grid_sync();

    // ---- Phase C: gather min/max, quantize strip into registers, seed alpha, partial sums ----
    {
        float mn = __int_as_float(0x7F800000);
        float mx = __int_as_float(0xFF800000);
        if (t < PBB) { float2 mm = __ldcg(&g_pmm[b * PBB + t]); mn = mm.x; mx = mm.y; }
#pragma unroll
        for (int o = 16; o; o >>= 1) {
            mn = fminf(mn, __shfl_xor_sync(0xffffffffu, mn, o));
            mx = fmaxf(mx, __shfl_xor_sync(0xffffffffu, mx, o));
        }
        if (lane == 0) { s_red[wrp] = mn; s_red[16 + wrp] = mx; }
        __syncthreads();
        if (t == 0) {
            for (int i = 1; i < 16; i++) { mn = fminf(mn, s_red[i]); mx = fmaxf(mx, s_red[16 + i]); }
            s_means[0] = mn;
            s_means[1] = __fadd_rn(__fsub_rn(mx, mn), 1e-12f);
        }
        __syncthreads();
        const float mnv = s_means[0], den = s_means[1];

        const float* fb = f + (size_t)b * CC * HW + (size_t)rr * WW + cb;
        float4 c0a = *(const float4*)(fb);
        float4 c0b = *(const float4*)(fb + 4);
        float4 c1a = *(const float4*)(fb + HW);
        float4 c1b = *(const float4*)(fb + HW + 4);
        float4 c2a = *(const float4*)(fb + 2 * HW);
        float4 c2b = *(const float4*)(fb + 2 * HW + 4);
        float t0v[8] = {c0a.x, c0a.y, c0a.z, c0a.w, c0b.x, c0b.y, c0b.z, c0b.w};
        float t1v[8] = {c1a.x, c1a.y, c1a.z, c1a.w, c1b.x, c1b.y, c1b.z, c1b.w};
        float t2v[8] = {c2a.x, c2a.y, c2a.z, c2a.w, c2b.x, c2b.y, c2b.z, c2b.w};

        const int* mb = mask + (size_t)b * HW + (size_t)rr * WW + cb;
        int4 m0 = *(const int4*)(mb);
        int4 m1 = *(const int4*)(mb + 4);
        int mk[8] = {m0.x, m0.y, m0.z, m0.w, m1.x, m1.y, m1.z, m1.w};

        unsigned aw0 = 0, aw1 = 0;
        unsigned s0 = 0, s1 = 0, s2 = 0, f0 = 0, f1 = 0, f2 = 0, fc = 0;
#pragma unroll
        for (int k = 0; k < 8; k++) {
            fv0[k] = quantize(t0v[k], mnv, den);
            fv1[k] = quantize(t1v[k], mnv, den);
            fv2[k] = quantize(t2v[k], mnv, den);
            unsigned u0 = (unsigned)fv0[k], u1 = (unsigned)fv1[k], u2 = (unsigned)fv2[k];
            const int sh = 8 * (k & 3);
            if (k < 4) { p0lo |= u0 << sh; p1lo |= u1 << sh; p2lo |= u2 << sh; }
            else       { p0hi |= u0 << sh; p1hi |= u1 << sh; p2hi |= u2 << sh; }
            int c = cb + k;
            bool center = (rr >= C0 && rr < C1 && c >= C0 && c < C1);
            bool border = (rr < BORD || rr >= HH - BORD || c < BORD || c >= WW - BORD);
            unsigned al = center ? 1u : (border ? 0u : (mk[k] == 1 ? 1u : 0u));
            if (center || border) fixedm |= 1u << k;
            if (center)           ffgm   |= 1u << k;
            if (k < 4) aw0 |= al << sh; else aw1 |= al << sh;
            s0 += u0; s1 += u1; s2 += u2;
            if (al) { f0 += u0; f1 += u1; f2 += u2; fc++; }
        }
        *(uint2*)&s_alpha[0][ty + 1][cb] = make_uint2(aw0, aw1);
        if (ty == 0)       *(uint2*)&g_halo[0][b][rs][cb]     = make_uint2(aw0, aw1);
        if (ty == RPB - 1) *(uint2*)&g_halo[0][b][rs + 7][cb] = make_uint2(aw0, aw1);

        s0 = warpSum(s0); s1 = warpSum(s1); s2 = warpSum(s2);
        f0 = warpSum(f0); f1 = warpSum(f1); f2 = warpSum(f2); fc = warpSum(fc);
        if (lane == 0) {
            atomicAdd(&s_acc[0], s0); atomicAdd(&s_acc[1], s1); atomicAdd(&s_acc[2], s2);
            atomicAdd(&s_acc[3], f0); atomicAdd(&s_acc[4], f1); atomicAdd(&s_acc[5], f2);
            atomicAdd(&s_acc[6], fc);
        }
        __syncthreads();
        if (t == 0) {
            g_ptot[blockIdx.x]   = make_uint4(s_acc[0], s_acc[1], s_acc[2], 0u);
            g_pfg[0][blockIdx.x] = make_uint4(s_acc[3], s_acc[4], s_acc[5], s_acc[6]);
#pragma unroll
            for (int i = 0; i < 8; i++) s_acc[i] = 0u;
        }
    }
    grid_sync();

    // ---- gather batch totals once ----
    {
        unsigned q0 = 0, q1 = 0, q2 = 0;
        if (t < PBB) { uint4 pt = __ldcg(&g_ptot[b * PBB + t]); q0 = pt.x; q1 = pt.y; q2 = pt.z; }
        q0 = warpSum(q0); q1 = warpSum(q1); q2 = warpSum(q2);
        if (lane == 0) { atomicAdd(&s_acc[0], q0); atomicAdd(&s_acc[1], q1); atomicAdd(&s_acc[2], q2); }
        __syncthreads();
        if (t == 0) {
            s_tot[0] = s_acc[0]; s_tot[1] = s_acc[1]; s_tot[2] = s_acc[2];
            s_acc[0] = s_acc[1] = s_acc[2] = 0u;
        }
        __syncthreads();
    }

    // ---- Phase D: 5 ICM iterations, SMEM-resident alpha, halo rows through L2 ----
    const int up_r = (rs == 0)        ? 0      : rs - 1;
    const int dn_r = (rs + RPB >= HH) ? HH - 1 : rs + RPB;

    for (int it = 0; it < ITERS; it++) {
        const int pp = it & 1;
        const bool last = (it == ITERS - 1);

        // gather this iteration's fg partials (s_acc[0..3] are zero here)
        {
            unsigned q0 = 0, q1 = 0, q2 = 0, q3 = 0;
            if (t < PBB) {
                uint4 pf = __ldcg(&g_pfg[it][b * PBB + t]);
                q0 = pf.x; q1 = pf.y; q2 = pf.z; q3 = pf.w;
            }
            q0 = warpSum(q0); q1 = warpSum(q1); q2 = warpSum(q2); q3 = warpSum(q3);
            if (lane == 0) {
                atomicAdd(&s_acc[0], q0); atomicAdd(&s_acc[1], q1);
                atomicAdd(&s_acc[2], q2); atomicAdd(&s_acc[3], q3);
            }
        }
        // load halo rows (written by neighbor strips last iteration)
        if (t < 64) {
            *(uint2*)&s_alpha[pp][0][t * 8] =
                __ldcg((const uint2*)&g_halo[pp][b][up_r][t * 8]);
        } else if (t < 128) {
            *(uint2*)&s_alpha[pp][RPB + 1][(t - 64) * 8] =
                __ldcg((const uint2*)&g_halo[pp][b][dn_r][(t - 64) * 8]);
        }
        __syncthreads();

        if (t == 0) {
            unsigned fs0 = s_acc[0], fs1 = s_acc[1], fs2 = s_acc[2], fcn = s_acc[3];
            // JAX: mean = f32(exact integer sum) / (f32(count) + 1e-6)
            float fden = __fadd_rn(__uint2float_rn(fcn), 1e-6f);
            s_means[0] = __fdiv_rn(__uint2float_rn(fs0), fden);
            s_means[1] = __fdiv_rn(__uint2float_rn(fs1), fden);
            s_means[2] = __fdiv_rn(__uint2float_rn(fs2), fden);
            float bden = __fadd_rn(__uint2float_rn((unsigned)HW - fcn), 1e-6f);
            s_means[3] = __fdiv_rn(__uint2float_rn(s_tot[0] - fs0), bden);
            s_means[4] = __fdiv_rn(__uint2float_rn(s_tot[1] - fs1), bden);
            s_means[5] = __fdiv_rn(__uint2float_rn(s_tot[2] - fs2), bden);
            s_acc[0] = s_acc[1] = s_acc[2] = s_acc[3] = 0u;
        }
        __syncthreads();
        const float fm0 = s_means[0], fm1 = s_means[1], fm2 = s_means[2];
        const float bm0 = s_means[3], bm1 = s_means[4], bm2 = s_means[5];

        // neighbor sums for all 8 pixels via SIMD byte adds (each byte <= 4)
        uint2 cw = *(const uint2*)&s_alpha[pp][ty + 1][cb];
        uint2 uw = *(const uint2*)&s_alpha[pp][ty][cb];
        uint2 dw = *(const uint2*)&s_alpha[pp][ty + 2][cb];
        unsigned lb = (cb == 0)      ? (cw.x & 0xFFu) : (unsigned)s_alpha[pp][ty + 1][cb - 1];
        unsigned rbv = (cb == WW - 8) ? (cw.y >> 24)   : (unsigned)s_alpha[pp][ty + 1][cb + 8];
        unsigned lw0 = (cw.x << 8) | lb;
        unsigned lw1 = (cw.y << 8) | (cw.x >> 24);
        unsigned rw0 = (cw.x >> 8) | (cw.y << 24);
        unsigned rw1 = (cw.y >> 8) | (rbv << 24);
        unsigned ns0 = uw.x + dw.x + lw0 + rw0;
        unsigned ns1 = uw.y + dw.y + lw1 + rw1;

        unsigned aw0 = 0, aw1 = 0;
        unsigned a0 = 0, a1 = 0, a2 = 0, ac = 0;
        float of[8];
#pragma unroll
        for (int k = 0; k < 8; k++) {
            const int sh = 8 * (k & 3);
            unsigned na;
            if ((fixedm >> k) & 1u) {
                na = (ffgm >> k) & 1u;
            } else {
                unsigned nsum = ((k < 4 ? ns0 : ns1) >> sh) & 0xFFu;
                float d0 = __fsub_rn(fv0[k], fm0);
                float d1 = __fsub_rn(fv1[k], fm1);
                float d2 = __fsub_rn(fv2[k], fm2);
                float dfg = __fadd_rn(__fadd_rn(__fmul_rn(d0, d0), __fmul_rn(d1, d1)), __fmul_rn(d2, d2));
                float e0 = __fsub_rn(fv0[k], bm0);
                float e1 = __fsub_rn(fv1[k], bm1);
                float e2 = __fsub_rn(fv2[k], bm2);
                float dbg = __fadd_rn(__fadd_rn(__fmul_rn(e0, e0), __fmul_rn(e1, e1)), __fmul_rn(e2, e2));
                float nb = __fmul_rn(__uint2float_rn(nsum), 0.25f);
                float smv = __fmul_rn(50.0f, __fsub_rn(__fmul_rn(2.0f, nb), 1.0f));
                float score = __fadd_rn(__fsub_rn(dbg, dfg), smv);
                na = (score > 0.0f) ? 1u : 0u;
            }
            if (last) {
                of[k] = (float)na;
            } else {
                if (k < 4) aw0 |= na << sh; else aw1 |= na << sh;
                if (na) {
                    a0 += ((k < 4 ? p0lo : p0hi) >> sh) & 0xFFu;
                    a1 += ((k < 4 ? p1lo : p1hi) >> sh) & 0xFFu;
                    a2 += ((k < 4 ? p2lo : p2hi) >> sh) & 0xFFu;
                    ac++;
                }
            }
        }

        if (last) {
            float* ob = out + (size_t)b * HW + (size_t)rr * WW + cb;
            *(float4*)(ob)     = make_float4(of[0], of[1], of[2], of[3]);
            *(float4*)(ob + 4) = make_float4(of[4], of[5], of[6], of[7]);
        } else {
            *(uint2*)&s_alpha[pp ^ 1][ty + 1][cb] = make_uint2(aw0, aw1);
            if (ty == 0)       *(uint2*)&g_halo[pp ^ 1][b][rs][cb]     = make_uint2(aw0, aw1);
            if (ty == RPB - 1) *(uint2*)&g_halo[pp ^ 1][b][rs + 7][cb] = make_uint2(aw0, aw1);
            a0 = warpSum(a0); a1 = warpSum(a1); a2 = warpSum(a2); ac = warpSum(ac);
            if (lane == 0) {
                atomicAdd(&s_acc[4], a0); atomicAdd(&s_acc[5], a1);
                atomicAdd(&s_acc[6], a2); atomicAdd(&s_acc[7], ac);
            }
            __syncthreads();
            if (t == 0) {
                g_pfg[it + 1][blockIdx.x] = make_uint4(s_acc[4], s_acc[5], s_acc[6], s_acc[7]);
                s_acc[4] = s_acc[5] = s_acc[6] = s_acc[7] = 0u;
            }
            grid_sync();
        }
    }
}

// ---------------- launch ----------------
extern "C" void kernel_launch(void* const* d_in, const int* in_sizes, int n_in,
                              void* d_out, int out_size) {
    const float* features = (const float*)d_in[0];
    const int*   mask     = (const int*)d_in[1];
    float*       out      = (float*)d_out;
    gc_kernel<<<NBLK, NTHR>>>(features, mask, out);
}

// round 10
// speedup vs baseline: 2.1116x; 1.2913x over previous
#include <cuda_runtime.h>

#define BB 2
#define CC 256
#define HH 512
#define WW 512
#define HW (HH*WW)
#define ITERS 5

// trimap constants (int(512*0.1)=51, int(512*0.45)=230, int(512*0.55)=281)
#define BORD 51
#define C0 230
#define C1 281

#define PBB 128             // blocks per batch
#define NBLK (BB*PBB)       // 256 blocks, 2 per SM
#define NTHR 512
#define RPB 4               // rows per strip (128 strips * 4 = 512)
#define TPB (PBB*NTHR)      // 65536 threads per batch
#define NSYNC 6             // sync 0 = minmax, sync s(1..5) = means for iter s-1

// ---------------- scratch (no allocations allowed) ----------------
__device__ unsigned           g_cnt[NSYNC][BB];    // arrival counters (self-reset)
__device__ volatile unsigned  g_flag[NSYNC][BB];   // release flags (chain-reset)
__device__ int                g_mm[BB][2] = {{0x7F800000, (int)0xFF800000},
                                             {0x7F800000, (int)0xFF800000}};
__device__ unsigned long long g_sA[ITERS][BB];     // fg sums packed: s0 | s1<<32
__device__ unsigned long long g_sB[ITERS][BB];     // fg sums packed: s2 | cnt<<32
__device__ unsigned long long g_tA[BB];            // totals packed: t0 | t1<<32
__device__ unsigned long long g_tB[BB];            // totals packed: t2
__device__ unsigned           g_totf[BB][3];       // unpacked totals (written once/replay)
__device__ float              g_bcast[BB][8];      // [0..5] means, [6]=mn, [7]=den
__device__ __align__(16) unsigned char g_halo[2][BB][HH][WW];  // only strip-edge rows used

// ---------------- helpers ----------------
__device__ __forceinline__ void atomicMinF(int* addr, float v) {
    if (v >= 0.0f) atomicMin(addr, __float_as_int(v));
    else           atomicMax((unsigned*)addr, (unsigned)__float_as_int(v));
}
__device__ __forceinline__ void atomicMaxF(int* addr, float v) {
    if (v >= 0.0f) atomicMax(addr, __float_as_int(v));
    else           atomicMin((unsigned*)addr, (unsigned)__float_as_int(v));
}
__device__ __forceinline__ unsigned warpSum(unsigned v) {
#pragma unroll
    for (int o = 16; o; o >>= 1) v += __shfl_xor_sync(0xffffffffu, v, o);
    return v;
}
__device__ __forceinline__ float quantize(float x, float mn, float den) {
    float v = __fmul_rn(__fdiv_rn(__fsub_rn(x, mn), den), 255.0f);
    return fminf(fmaxf(floorf(v), 0.0f), 255.0f);
}

// ---------------- the single persistent kernel ----------------
__global__ void __launch_bounds__(NTHR, 2)
gc_kernel(const float* __restrict__ f, const int* __restrict__ mask,
          float* __restrict__ out)
{
    const int b    = blockIdx.x / PBB;
    const int blk  = blockIdx.x % PBB;
    const int t    = threadIdx.x;
    const int lane = t & 31;
    const int wrp  = t >> 5;
    const int ty   = t >> 7;            // row within strip (0..3)
    const int tx   = t & 127;           // column group (4 px each)
    const int rs   = blk * RPB;         // strip start row
    const int rr   = rs + ty;
    const int cb   = tx * 4;

    __shared__ __align__(16) unsigned char s_alpha[2][RPB + 2][WW];
    __shared__ unsigned s_acc[8];
    __shared__ float    s_means[8];
    __shared__ float    s_red[32];

    const int up_r = (rs == 0)          ? 0      : rs - 1;
    const int dn_r = (rs + RPB >= HH)   ? HH - 1 : rs + RPB;

    // per-thread persistent pixel data
    float fv0[4], fv1[4], fv2[4];
    unsigned p0 = 0, p1 = 0, p2 = 0;     // packed pixel bytes per channel
    unsigned fixedm = 0, ffgm = 0;

    if (t < 8) s_acc[t] = 0u;

    // ---- Phase B: per-batch min/max over first 3 channels (DRAM read) ----
    {
        const float4* p = (const float4*)(f + (size_t)b * CC * HW);
        const int n = 3 * HW / 4;
        float mn = __int_as_float(0x7F800000);
        float mx = __int_as_float(0xFF800000);
        for (int i = blk * NTHR + t; i < n; i += TPB) {
            float4 v = p[i];
            mn = fminf(mn, fminf(fminf(v.x, v.y), fminf(v.z, v.w)));
            mx = fmaxf(mx, fmaxf(fmaxf(v.x, v.y), fmaxf(v.z, v.w)));
        }
#pragma unroll
        for (int o = 16; o; o >>= 1) {
            mn = fminf(mn, __shfl_xor_sync(0xffffffffu, mn, o));
            mx = fmaxf(mx, __shfl_xor_sync(0xffffffffu, mx, o));
        }
        if (lane == 0) { s_red[wrp] = mn; s_red[16 + wrp] = mx; }
        __syncthreads();
        if (t == 0) {
            for (int i = 1; i < 16; i++) { mn = fminf(mn, s_red[i]); mx = fmaxf(mx, s_red[16 + i]); }
            atomicMinF(&g_mm[b][0], mn);
            atomicMaxF(&g_mm[b][1], mx);
            __threadfence();
            if (atomicAdd(&g_cnt[0][b], 1u) == PBB - 1) {
                // releaser: compute mn/den, reset slots for next replay, release
                float mnv = __int_as_float(g_mm[b][0]);
                float mxv = __int_as_float(g_mm[b][1]);
                g_bcast[b][6] = mnv;
                g_bcast[b][7] = __fadd_rn(__fsub_rn(mxv, mnv), 1e-12f);
                g_mm[b][0] = 0x7F800000; g_mm[b][1] = (int)0xFF800000;
                g_cnt[0][b] = 0u;
                g_flag[NSYNC - 1][b] = 0u;      // clear stale last flag from prev replay
                __threadfence();
                g_flag[0][b] = 1u;
            }
            while (g_flag[0][b] == 0u) { }
            __threadfence();
            s_means[6] = __ldcg(&g_bcast[b][6]);
            s_means[7] = __ldcg(&g_bcast[b][7]);
        }
        __syncthreads();
    }

    // ---- Phase C: quantize strip into registers, seed alpha, accumulate sums ----
    {
        const float mnv = s_means[6], den = s_means[7];
        const float* fb = f + (size_t)b * CC * HW + (size_t)rr * WW + cb;
        float4 c0 = *(const float4*)(fb);
        float4 c1 = *(const float4*)(fb + HW);
        float4 c2 = *(const float4*)(fb + 2 * HW);
        float t0v[4] = {c0.x, c0.y, c0.z, c0.w};
        float t1v[4] = {c1.x, c1.y, c1.z, c1.w};
        float t2v[4] = {c2.x, c2.y, c2.z, c2.w};
        int4 m = *(const int4*)(mask + (size_t)b * HW + (size_t)rr * WW + cb);
        int mk[4] = {m.x, m.y, m.z, m.w};

        unsigned aw = 0;
        unsigned s0 = 0, s1 = 0, s2 = 0, f0 = 0, f1 = 0, f2 = 0, fc = 0;
#pragma unroll
        for (int k = 0; k < 4; k++) {
            fv0[k] = quantize(t0v[k], mnv, den);
            fv1[k] = quantize(t1v[k], mnv, den);
            fv2[k] = quantize(t2v[k], mnv, den);
            unsigned u0 = (unsigned)fv0[k], u1 = (unsigned)fv1[k], u2 = (unsigned)fv2[k];
            const int sh = 8 * k;
            p0 |= u0 << sh; p1 |= u1 << sh; p2 |= u2 << sh;
            int c = cb + k;
            bool center = (rr >= C0 && rr < C1 && c >= C0 && c < C1);
            bool border = (rr < BORD || rr >= HH - BORD || c < BORD || c >= WW - BORD);
            unsigned al = center ? 1u : (border ? 0u : (mk[k] == 1 ? 1u : 0u));
            if (center || border) fixedm |= 1u << k;
            if (center)           ffgm   |= 1u << k;
            aw |= al << sh;
            s0 += u0; s1 += u1; s2 += u2;
            if (al) { f0 += u0; f1 += u1; f2 += u2; fc++; }
        }
        *(unsigned*)&s_alpha[0][ty + 1][cb] = aw;
        if (ty == 0)       *(unsigned*)&g_halo[0][b][rs][cb]           = aw;
        if (ty == RPB - 1) *(unsigned*)&g_halo[0][b][rs + RPB - 1][cb] = aw;

        s0 = warpSum(s0); s1 = warpSum(s1); s2 = warpSum(s2);
        f0 = warpSum(f0); f1 = warpSum(f1); f2 = warpSum(f2); fc = warpSum(fc);
        __threadfence();                               // halo stores -> L2 before arrive
        if (lane == 0) {
            atomicAdd(&s_acc[0], s0); atomicAdd(&s_acc[1], s1); atomicAdd(&s_acc[2], s2);
            atomicAdd(&s_acc[3], f0); atomicAdd(&s_acc[4], f1); atomicAdd(&s_acc[5], f2);
            atomicAdd(&s_acc[6], fc);
        }
        __syncthreads();
        if (t == 0) {
            unsigned long long tA = (unsigned long long)s_acc[0] | ((unsigned long long)s_acc[1] << 32);
            unsigned long long tB = (unsigned long long)s_acc[2];
            unsigned long long sA = (unsigned long long)s_acc[3] | ((unsigned long long)s_acc[4] << 32);
            unsigned long long sB = (unsigned long long)s_acc[5] | ((unsigned long long)s_acc[6] << 32);
            atomicAdd(&g_tA[b], tA); atomicAdd(&g_tB[b], tB);
            atomicAdd(&g_sA[0][b], sA); atomicAdd(&g_sB[0][b], sB);
            if (atomicAdd(&g_cnt[1][b], 1u) == PBB - 1) {
                unsigned long long TA = __ldcg(&g_tA[b]), TB = __ldcg(&g_tB[b]);
                unsigned long long SA = __ldcg(&g_sA[0][b]), SB = __ldcg(&g_sB[0][b]);
                unsigned t0s = (unsigned)TA, t1s = (unsigned)(TA >> 32), t2s = (unsigned)TB;
                unsigned fs0 = (unsigned)SA, fs1 = (unsigned)(SA >> 32);
                unsigned fs2 = (unsigned)SB, fcn = (unsigned)(SB >> 32);
                g_totf[b][0] = t0s; g_totf[b][1] = t1s; g_totf[b][2] = t2s;
                float fden = __fadd_rn(__uint2float_rn(fcn), 1e-6f);
                g_bcast[b][0] = __fdiv_rn(__uint2float_rn(fs0), fden);
                g_bcast[b][1] = __fdiv_rn(__uint2float_rn(fs1), fden);
                g_bcast[b][2] = __fdiv_rn(__uint2float_rn(fs2), fden);
                float bden = __fadd_rn(__uint2float_rn((unsigned)HW - fcn), 1e-6f);
                g_bcast[b][3] = __fdiv_rn(__uint2float_rn(t0s - fs0), bden);
                g_bcast[b][4] = __fdiv_rn(__uint2float_rn(t1s - fs1), bden);
                g_bcast[b][5] = __fdiv_rn(__uint2float_rn(t2s - fs2), bden);
                g_tA[b] = 0ull; g_tB[b] = 0ull;
                g_sA[0][b] = 0ull; g_sB[0][b] = 0ull;
                g_cnt[1][b] = 0u;
                g_flag[0][b] = 0u;
                __threadfence();
                g_flag[1][b] = 1u;
            }
        }
    }

    // ---- Phase D: 5 ICM iterations with one-shot mean syncs ----
    for (int it = 0; it < ITERS; it++) {
        const int pp = it & 1;
        const bool last = (it == ITERS - 1);

        // wait for this iteration's means, broadcast into SMEM
        if (t == 0) {
            while (g_flag[it + 1][b] == 0u) { }
            __threadfence();
#pragma unroll
            for (int j = 0; j < 6; j++) s_means[j] = __ldcg(&g_bcast[b][j]);
        }
        if (t >= 480 && t < 488) s_acc[t - 480] = 0u;   // re-zero accumulators (any warp != 0)
        __syncthreads();

        // load halo rows (neighbors' edge rows from previous iteration), L2-coherent
        if (t < 32) {
            ((uint4*)&s_alpha[pp][0][0])[t] = __ldcg(((const uint4*)&g_halo[pp][b][up_r][0]) + t);
        } else if (t < 64) {
            ((uint4*)&s_alpha[pp][RPB + 1][0])[t - 32] = __ldcg(((const uint4*)&g_halo[pp][b][dn_r][0]) + (t - 32));
        }
        __syncthreads();

        const float fm0 = s_means[0], fm1 = s_means[1], fm2 = s_means[2];
        const float bm0 = s_means[3], bm1 = s_means[4], bm2 = s_means[5];

        // neighbor sums for 4 pixels via SIMD byte adds (each byte <= 4)
        unsigned cw = *(const unsigned*)&s_alpha[pp][ty + 1][cb];
        unsigned uw = *(const unsigned*)&s_alpha[pp][ty][cb];
        unsigned dw = *(const unsigned*)&s_alpha[pp][ty + 2][cb];
        unsigned lb = (cb == 0)      ? (cw & 0xFFu) : (unsigned)s_alpha[pp][ty + 1][cb - 1];
        unsigned rb = (cb == WW - 4) ? (cw >> 24)   : (unsigned)s_alpha[pp][ty + 1][cb + 4];
        unsigned lw = (cw << 8) | lb;
        unsigned rw = (cw >> 8) | (rb << 24);
        unsigned ns = uw + dw + lw + rw;

        unsigned aw = 0;
        unsigned a0 = 0, a1 = 0, a2 = 0, ac = 0;
        float of[4];
#pragma unroll
        for (int k = 0; k < 4; k++) {
            const int sh = 8 * k;
            unsigned na;
            if ((fixedm >> k) & 1u) {
                na = (ffgm >> k) & 1u;
            } else {
                unsigned nsum = (ns >> sh) & 0xFFu;
                float d0 = __fsub_rn(fv0[k], fm0);
                float d1 = __fsub_rn(fv1[k], fm1);
                float d2 = __fsub_rn(fv2[k], fm2);
                float dfg = __fadd_rn(__fadd_rn(__fmul_rn(d0, d0), __fmul_rn(d1, d1)), __fmul_rn(d2, d2));
                float e0 = __fsub_rn(fv0[k], bm0);
                float e1 = __fsub_rn(fv1[k], bm1);
                float e2 = __fsub_rn(fv2[k], bm2);
                float dbg = __fadd_rn(__fadd_rn(__fmul_rn(e0, e0), __fmul_rn(e1, e1)), __fmul_rn(e2, e2));
                float nb = __fmul_rn(__uint2float_rn(nsum), 0.25f);
                float smv = __fmul_rn(50.0f, __fsub_rn(__fmul_rn(2.0f, nb), 1.0f));
                float score = __fadd_rn(__fsub_rn(dbg, dfg), smv);
                na = (score > 0.0f) ? 1u : 0u;
            }
            if (last) {
                of[k] = (float)na;
            } else {
                aw |= na << sh;
                if (na) {
                    a0 += (p0 >> sh) & 0xFFu;
                    a1 += (p1 >> sh) & 0xFFu;
                    a2 += (p2 >> sh) & 0xFFu;
                    ac++;
                }
            }
        }

        if (last) {
            float* ob = out + (size_t)b * HW + (size_t)rr * WW + cb;
            *(float4*)ob = make_float4(of[0], of[1], of[2], of[3]);
        } else {
            *(unsigned*)&s_alpha[pp ^ 1][ty + 1][cb] = aw;
            if (ty == 0)       *(unsigned*)&g_halo[pp ^ 1][b][rs][cb]           = aw;
            if (ty == RPB - 1) *(unsigned*)&g_halo[pp ^ 1][b][rs + RPB - 1][cb] = aw;
            a0 = warpSum(a0); a1 = warpSum(a1); a2 = warpSum(a2); ac = warpSum(ac);
            __threadfence();                           // halo stores -> L2 before arrive
            if (lane == 0) {
                atomicAdd(&s_acc[0], a0); atomicAdd(&s_acc[1], a1);
                atomicAdd(&s_acc[2], a2); atomicAdd(&s_acc[3], ac);
            }
            __syncthreads();
            if (t == 0) {
                unsigned long long sA = (unsigned long long)s_acc[0] | ((unsigned long long)s_acc[1] << 32);
                unsigned long long sB = (unsigned long long)s_acc[2] | ((unsigned long long)s_acc[3] << 32);
                atomicAdd(&g_sA[it + 1][b], sA);
                atomicAdd(&g_sB[it + 1][b], sB);
                if (atomicAdd(&g_cnt[it + 2][b], 1u) == PBB - 1) {
                    unsigned long long SA = __ldcg(&g_sA[it + 1][b]);
                    unsigned long long SB = __ldcg(&g_sB[it + 1][b]);
                    unsigned fs0 = (unsigned)SA, fs1 = (unsigned)(SA >> 32);
                    unsigned fs2 = (unsigned)SB, fcn = (unsigned)(SB >> 32);
                    unsigned t0s = __ldcg(&g_totf[b][0]);
                    unsigned t1s = __ldcg(&g_totf[b][1]);
                    unsigned t2s = __ldcg(&g_totf[b][2]);
                    float fden = __fadd_rn(__uint2float_rn(fcn), 1e-6f);
                    g_bcast[b][0] = __fdiv_rn(__uint2float_rn(fs0), fden);
                    g_bcast[b][1] = __fdiv_rn(__uint2float_rn(fs1), fden);
                    g_bcast[b][2] = __fdiv_rn(__uint2float_rn(fs2), fden);
                    float bden = __fadd_rn(__uint2float_rn((unsigned)HW - fcn), 1e-6f);
                    g_bcast[b][3] = __fdiv_rn(__uint2float_rn(t0s - fs0), bden);
                    g_bcast[b][4] = __fdiv_rn(__uint2float_rn(t1s - fs1), bden);
                    g_bcast[b][5] = __fdiv_rn(__uint2float_rn(t2s - fs2), bden);
                    g_sA[it + 1][b] = 0ull; g_sB[it + 1][b] = 0ull;
                    g_cnt[it + 2][b] = 0u;
                    g_flag[it + 1][b] = 0u;
                    __threadfence();
                    g_flag[it + 2][b] = 1u;
                }
            }
        }
    }
}

// ---------------- launch ----------------
extern "C" void kernel_launch(void* const* d_in, const int* in_sizes, int n_in,
                              void* d_out, int out_size) {
    const float* features = (const float*)d_in[0];
    const int*   mask     = (const int*)d_in[1];
    float*       out      = (float*)d_out;
    gc_kernel<<<NBLK, NTHR>>>(features, mask, out);
}